// round 1
// baseline (speedup 1.0000x reference)
#include <cuda_runtime.h>
#include <math.h>

// Problem constants
#define DD 300
#define HH 4
#define HD 1200           // H*D
#define MAXN 50000
#define MAXE 200000

// ---------------- scratch (static device globals; no allocation) ----------------
__device__ float    g_fsrc[(size_t)MAXN * HD];   // [N,H,D] = feat @ Wg
__device__ float    g_gat [(size_t)MAXN * HD];   // GAT output accumulator
__device__ float    g_el  [MAXN * HH];
__device__ float    g_er  [MAXN * HH];
__device__ float    g_e   [MAXE * HH];           // edge scores -> exp values
__device__ unsigned g_mkey[MAXN * HH];           // segment-max as monotone uint keys
__device__ float    g_z   [MAXN * HH];           // softmax denominator
__device__ float    g_neigh[(size_t)MAXN * DD];  // SAGE neighbor sum
__device__ float    g_deg [MAXN];                // in-degree on g1
__device__ float    g_sage[(size_t)MAXN * DD];

// monotone float<->uint mapping for atomicMax on float (handles negatives, -0)
__device__ __forceinline__ unsigned fkey(float f) {
    unsigned u = __float_as_uint(f);
    return (u & 0x80000000u) ? ~u : (u | 0x80000000u);
}
__device__ __forceinline__ float funkey(unsigned k) {
    return (k & 0x80000000u) ? __uint_as_float(k ^ 0x80000000u) : __uint_as_float(~k);
}

// ---------------- GEMM: C[M,Ncol] = op(A)[M,K] @ B[K,Ncol] (+bias) ----------------
// BM=BN=64, BK=20 (K=300 = 15*20 exact), 256 threads, 4x4 per-thread tile.
// If A2 != null: op(A)[m,k] = (A[m,k] + A2[m,k]) / (deg[m] + 1)   (fused SAGE gcn-mean)
#define BM 64
#define BN 64
#define BK 20
#define ASTRIDE 68  // padded to dodge bank conflicts, keeps 16B alignment

__global__ void gemm64_kernel(const float* __restrict__ A,
                              const float* __restrict__ B,
                              float* __restrict__ C,
                              int M, int Ncol, int K,
                              const float* __restrict__ A2,
                              const float* __restrict__ deg,
                              const float* __restrict__ bias)
{
    __shared__ float As[BK][ASTRIDE];   // transposed: As[k][m]
    __shared__ float Bs[BK][BN];

    const int tid = threadIdx.x;
    const int tx = tid & 15;
    const int ty = tid >> 4;
    const int rowBase = blockIdx.y * BM;
    const int colBase = blockIdx.x * BN;

    float acc[4][4] = {};

    for (int kt = 0; kt < K; kt += BK) {
        // load A tile (64 x 20), store transposed
        #pragma unroll
        for (int i = tid; i < BM * BK; i += 256) {
            int r = i / BK, c = i % BK;
            int gr = rowBase + r;
            float v = 0.f;
            if (gr < M) {
                size_t gi = (size_t)gr * K + kt + c;
                v = A[gi];
                if (A2) v = (v + A2[gi]) * (1.0f / (deg[gr] + 1.0f));
            }
            As[c][r] = v;
        }
        // load B tile (20 x 64)
        #pragma unroll
        for (int i = tid; i < BK * BN; i += 256) {
            int r = i / BN, c = i % BN;
            int gc = colBase + c;
            Bs[r][c] = (gc < Ncol) ? B[(size_t)(kt + r) * Ncol + gc] : 0.f;
        }
        __syncthreads();

        #pragma unroll
        for (int kk = 0; kk < BK; kk++) {
            float4 a = *(const float4*)&As[kk][ty * 4];
            float4 b = *(const float4*)&Bs[kk][tx * 4];
            float av[4] = {a.x, a.y, a.z, a.w};
            float bv[4] = {b.x, b.y, b.z, b.w};
            #pragma unroll
            for (int i = 0; i < 4; i++)
                #pragma unroll
                for (int j = 0; j < 4; j++)
                    acc[i][j] += av[i] * bv[j];
        }
        __syncthreads();
    }

    #pragma unroll
    for (int i = 0; i < 4; i++) {
        int gr = rowBase + ty * 4 + i;
        if (gr >= M) continue;
        #pragma unroll
        for (int j = 0; j < 4; j++) {
            int gc = colBase + tx * 4 + j;
            if (gc < Ncol) {
                float v = acc[i][j];
                if (bias) v += bias[gc];
                C[(size_t)gr * Ncol + gc] = v;
            }
        }
    }
}

// ---------------- el/er: per-(node,head) dot with attn_l / attn_r ----------------
__global__ void el_er_kernel(const float* __restrict__ fsrc,
                             const float* __restrict__ attn_l,
                             const float* __restrict__ attn_r,
                             float* __restrict__ el, float* __restrict__ er)
{
    int n = blockIdx.x;
    int w = threadIdx.x >> 5;      // head = warp id (4 warps)
    int lane = threadIdx.x & 31;
    const float* fr = fsrc + (size_t)n * HD + w * DD;
    const float* al = attn_l + w * DD;
    const float* ar = attn_r + w * DD;
    float sl = 0.f, sr = 0.f;
    for (int d = lane; d < DD; d += 32) {
        float f = fr[d];
        sl += f * al[d];
        sr += f * ar[d];
    }
    #pragma unroll
    for (int o = 16; o; o >>= 1) {
        sl += __shfl_down_sync(0xffffffffu, sl, o);
        sr += __shfl_down_sync(0xffffffffu, sr, o);
    }
    if (lane == 0) {
        el[n * HH + w] = sl;
        er[n * HH + w] = sr;
    }
}

// ---------------- edge scores + segment max ----------------
__global__ void edge_score_kernel(const float* __restrict__ el,
                                  const float* __restrict__ er,
                                  const int* __restrict__ src,
                                  const int* __restrict__ dst,
                                  float* __restrict__ ebuf,
                                  unsigned* __restrict__ mkey, int E)
{
    int i = blockIdx.x * blockDim.x + threadIdx.x;
    if (i >= E) return;
    int s = src[i], d = dst[i];
    float4 l = ((const float4*)el)[s];
    float4 r = ((const float4*)er)[d];
    float4 x;
    x.x = l.x + r.x; x.x = x.x > 0.f ? x.x : 0.2f * x.x;
    x.y = l.y + r.y; x.y = x.y > 0.f ? x.y : 0.2f * x.y;
    x.z = l.z + r.z; x.z = x.z > 0.f ? x.z : 0.2f * x.z;
    x.w = l.w + r.w; x.w = x.w > 0.f ? x.w : 0.2f * x.w;
    ((float4*)ebuf)[i] = x;
    atomicMax(&mkey[d * HH + 0], fkey(x.x));
    atomicMax(&mkey[d * HH + 1], fkey(x.y));
    atomicMax(&mkey[d * HH + 2], fkey(x.z));
    atomicMax(&mkey[d * HH + 3], fkey(x.w));
}

// ---------------- exp(e - m) and segment sum z ----------------
__global__ void edge_exp_kernel(float* __restrict__ ebuf,
                                const int* __restrict__ dst,
                                const unsigned* __restrict__ mkey,
                                float* __restrict__ z, int E)
{
    int i = blockIdx.x * blockDim.x + threadIdx.x;
    if (i >= E) return;
    int d = dst[i];
    float4 ev = ((const float4*)ebuf)[i];
    float4 x;
    x.x = expf(ev.x - funkey(mkey[d * HH + 0]));
    x.y = expf(ev.y - funkey(mkey[d * HH + 1]));
    x.z = expf(ev.z - funkey(mkey[d * HH + 2]));
    x.w = expf(ev.w - funkey(mkey[d * HH + 3]));
    ((float4*)ebuf)[i] = x;
    atomicAdd(&z[d * HH + 0], x.x);
    atomicAdd(&z[d * HH + 1], x.y);
    atomicAdd(&z[d * HH + 2], x.z);
    atomicAdd(&z[d * HH + 3], x.w);
}

// ---------------- GAT weighted aggregation: gat[dst] += alpha * fsrc[src] ----------------
__global__ void gat_agg_kernel(const float* __restrict__ exbuf,
                               const float* __restrict__ z,
                               const float* __restrict__ fsrc,
                               const int* __restrict__ src,
                               const int* __restrict__ dst,
                               float* __restrict__ gat)
{
    int e = blockIdx.x;
    int s = src[e], d = dst[e];
    __shared__ float sa[HH];
    if (threadIdx.x < HH)
        sa[threadIdx.x] = exbuf[e * HH + threadIdx.x] / z[d * HH + threadIdx.x];
    __syncthreads();
    const float* fr = fsrc + (size_t)s * HD;
    float* gr = gat + (size_t)d * HD;
    for (int idx = threadIdx.x; idx < HD; idx += blockDim.x)
        atomicAdd(&gr[idx], sa[idx / DD] * fr[idx]);
}

// ---------------- SAGE: neigh[dst1] += feat[src1]; deg[dst1] += 1 ----------------
__global__ void sage_agg_kernel(const float* __restrict__ feat,
                                const int* __restrict__ src1,
                                const int* __restrict__ dst1,
                                float* __restrict__ neigh,
                                float* __restrict__ deg)
{
    int e = blockIdx.x;
    int s = src1[e], d = dst1[e];
    const float* fr = feat + (size_t)s * DD;
    float* nr = neigh + (size_t)d * DD;
    for (int idx = threadIdx.x; idx < DD; idx += blockDim.x)
        atomicAdd(&nr[idx], fr[idx]);
    if (threadIdx.x == 0) atomicAdd(&deg[d], 1.0f);
}

// ---------------- gated head sum + residual ----------------
__global__ void final_kernel(const float* __restrict__ feat,
                             const float* __restrict__ gat,
                             const float* __restrict__ sage,
                             const float* __restrict__ b_gat,
                             const float* __restrict__ Whw,
                             const float* __restrict__ bhw,
                             float* __restrict__ out)
{
    int n = blockIdx.x;
    int t = threadIdx.x;            // 256 threads
    int lane = t & 31;

    __shared__ float ssum[5];
    __shared__ float sw[5];
    if (t < 5) ssum[t] = 0.f;
    __syncthreads();

    float vals[2][5];
    float p[5] = {0.f, 0.f, 0.f, 0.f, 0.f};

    #pragma unroll
    for (int it = 0; it < 2; it++) {
        int d = t + it * 256;
        if (d < DD) {
            float wv = Whw[d];
            #pragma unroll
            for (int r = 0; r < 4; r++) {
                float v = gat[(size_t)n * HD + r * DD + d] + b_gat[r * DD + d];
                vals[it][r] = v;
                p[r] += v * wv;
            }
            float v4 = sage[(size_t)n * DD + d];
            vals[it][4] = v4;
            p[4] += v4 * wv;
        }
    }
    #pragma unroll
    for (int o = 16; o; o >>= 1)
        #pragma unroll
        for (int r = 0; r < 5; r++)
            p[r] += __shfl_down_sync(0xffffffffu, p[r], o);
    if (lane == 0)
        #pragma unroll
        for (int r = 0; r < 5; r++) atomicAdd(&ssum[r], p[r]);
    __syncthreads();
    if (t < 5) sw[t] = 1.0f / (1.0f + expf(-(ssum[t] + bhw[0])));
    __syncthreads();

    float w0 = sw[0], w1 = sw[1], w2 = sw[2], w3 = sw[3], w4 = sw[4];
    #pragma unroll
    for (int it = 0; it < 2; it++) {
        int d = t + it * 256;
        if (d < DD) {
            float acc = feat[(size_t)n * DD + d];
            acc += vals[it][0] * w0 + vals[it][1] * w1 + vals[it][2] * w2
                 + vals[it][3] * w3 + vals[it][4] * w4;
            out[(size_t)n * DD + d] = acc;
        }
    }
}

// ---------------- launch ----------------
extern "C" void kernel_launch(void* const* d_in, const int* in_sizes, int n_in,
                              void* d_out, int out_size)
{
    const float* feat   = (const float*)d_in[0];
    const float* Wg     = (const float*)d_in[1];
    const float* attn_l = (const float*)d_in[2];
    const float* attn_r = (const float*)d_in[3];
    const float* b_gat  = (const float*)d_in[4];
    const float* Wsage  = (const float*)d_in[5];
    const float* b_sage = (const float*)d_in[6];
    const float* Whw    = (const float*)d_in[7];
    const float* bhw    = (const float*)d_in[8];
    const int*   src    = (const int*)d_in[9];
    const int*   dst    = (const int*)d_in[10];
    const int*   src1   = (const int*)d_in[11];
    const int*   dst1   = (const int*)d_in[12];
    float* out = (float*)d_out;

    const int N = in_sizes[0] / DD;
    const int E = in_sizes[9];

    float *fsrc, *gat, *el, *er, *ebuf, *z, *neigh, *deg, *sage;
    unsigned* mkey;
    cudaGetSymbolAddress((void**)&fsrc,  g_fsrc);
    cudaGetSymbolAddress((void**)&gat,   g_gat);
    cudaGetSymbolAddress((void**)&el,    g_el);
    cudaGetSymbolAddress((void**)&er,    g_er);
    cudaGetSymbolAddress((void**)&ebuf,  g_e);
    cudaGetSymbolAddress((void**)&mkey,  g_mkey);
    cudaGetSymbolAddress((void**)&z,     g_z);
    cudaGetSymbolAddress((void**)&neigh, g_neigh);
    cudaGetSymbolAddress((void**)&deg,   g_deg);
    cudaGetSymbolAddress((void**)&sage,  g_sage);

    // zero accumulators (graph-capturable memset nodes)
    cudaMemsetAsync(mkey,  0, (size_t)N * HH * sizeof(unsigned), 0);
    cudaMemsetAsync(z,     0, (size_t)N * HH * sizeof(float), 0);
    cudaMemsetAsync(gat,   0, (size_t)N * HD * sizeof(float), 0);
    cudaMemsetAsync(neigh, 0, (size_t)N * DD * sizeof(float), 0);
    cudaMemsetAsync(deg,   0, (size_t)N * sizeof(float), 0);

    // GEMM1: fsrc = feat @ Wg    [N,300] @ [300,1200]
    {
        dim3 grid((HD + BN - 1) / BN, (N + BM - 1) / BM);
        gemm64_kernel<<<grid, 256>>>(feat, Wg, fsrc, N, HD, DD,
                                     nullptr, nullptr, nullptr);
    }

    // el/er
    el_er_kernel<<<N, 128>>>(fsrc, attn_l, attn_r, el, er);

    // edge softmax pipeline
    edge_score_kernel<<<(E + 255) / 256, 256>>>(el, er, src, dst, ebuf, mkey, E);
    edge_exp_kernel<<<(E + 255) / 256, 256>>>(ebuf, dst, mkey, z, E);
    gat_agg_kernel<<<E, 256>>>(ebuf, z, fsrc, src, dst, gat);

    // SAGE aggregation (independent graph g1)
    sage_agg_kernel<<<E, 128>>>(feat, src1, dst1, neigh, deg);

    // GEMM2: sage = ((neigh + feat)/(deg+1)) @ Wsage + b_sage   [N,300]@[300,300]
    {
        dim3 grid((DD + BN - 1) / BN, (N + BM - 1) / BM);
        gemm64_kernel<<<grid, 256>>>(neigh, Wsage, sage, N, DD, DD,
                                     feat, deg, b_sage);
    }

    // gated multi-head sum + residual
    final_kernel<<<N, 256>>>(feat, gat, sage, b_gat, Whw, bhw, out);
}

// round 2
// speedup vs baseline: 1.7436x; 1.7436x over previous
#include <cuda_runtime.h>
#include <math.h>

// Problem constants
#define DD 300
#define HH 4
#define HD 1200           // H*D
#define MAXN 50000
#define MAXE 200000

// ---------------- scratch (static device globals; no allocation) ----------------
__device__ float    g_fsrc[(size_t)MAXN * HD];   // [N,H,D] = feat @ Wg
__device__ float    g_gat [(size_t)MAXN * HD];   // GAT output accumulator
__device__ float    g_el  [MAXN * HH];
__device__ float    g_er  [MAXN * HH];
__device__ float    g_e   [MAXE * HH];           // edge scores -> exp values
__device__ unsigned g_mkey[MAXN * HH];           // segment-max as monotone uint keys
__device__ float    g_z   [MAXN * HH];           // softmax denominator
__device__ float    g_neigh[(size_t)MAXN * DD];  // SAGE neighbor sum
__device__ float    g_deg [MAXN];                // in-degree on g1
__device__ float    g_sage[(size_t)MAXN * DD];

// monotone float<->uint mapping for atomicMax on float
__device__ __forceinline__ unsigned fkey(float f) {
    unsigned u = __float_as_uint(f);
    return (u & 0x80000000u) ? ~u : (u | 0x80000000u);
}
__device__ __forceinline__ float funkey(unsigned k) {
    return (k & 0x80000000u) ? __uint_as_float(k ^ 0x80000000u) : __uint_as_float(~k);
}

__device__ __forceinline__ unsigned f2tf32(float x) {
    unsigned r;
    asm("cvt.rna.tf32.f32 %0, %1;" : "=r"(r) : "f"(x));
    return r;
}

__device__ __forceinline__ void red_add_f32x4(float* p, float4 v) {
    asm volatile("red.global.add.v4.f32 [%0], {%1,%2,%3,%4};"
                 :: "l"(p), "f"(v.x), "f"(v.y), "f"(v.z), "f"(v.w) : "memory");
}

// ================= TF32 tensor-core GEMM =================
// C[M,Ncol] = op(A)[M,K] @ B[K,Ncol] (+bias)
// op(A) = (A + A2)/(deg+1) when FUSED (SAGE gcn-mean), else A.
// Block 128x64, BK=16, 256 threads (8 warps as 4m x 2n), warp tile 32x32.
// mma.sync.aligned.m16n8k8.row.col.f32.tf32.tf32.f32
// SMEM is stored in per-fragment order so the mainloop uses LDS.128/LDS.64.
#define GBM 128
#define GBN 64
#define GBK 16

template<bool FUSED>
__global__ __launch_bounds__(256) void gemm_tf32_kernel(
    const float* __restrict__ A, const float* __restrict__ B, float* __restrict__ C,
    int M, int Ncol, int K,
    const float* __restrict__ A2, const float* __restrict__ deg,
    const float* __restrict__ bias)
{
    // As: [mt(8)][ks(2)][lane(32)][4 regs]  (A fragments, tf32 bits)
    // Bs: [nt(8)][ks(2)][lane(32)][2 regs]
    __shared__ unsigned As[8 * 2 * 32 * 4];
    __shared__ unsigned Bs[8 * 2 * 32 * 2];

    const int tid  = threadIdx.x;
    const int lane = tid & 31;
    const int wid  = tid >> 5;
    const int wm   = wid & 3;      // warp m position (0..3)
    const int wn   = wid >> 2;     // warp n position (0..1)
    const int rowBase = blockIdx.y * GBM;
    const int colBase = blockIdx.x * GBN;

    float acc[2][4][4];
    #pragma unroll
    for (int i = 0; i < 2; i++)
        #pragma unroll
        for (int j = 0; j < 4; j++)
            #pragma unroll
            for (int r = 0; r < 4; r++) acc[i][j][r] = 0.f;

    // ---- global prefetch registers ----
    float4 ra[2];   // A: 2 float4 per thread (128x16 / 256)
    float4 rb;      // B: 1 float4 per thread (16x64 / 256)

    // A load mapping: idx = tid + 256*q ; r = idx>>2 (0..127), c4 = idx&3
    // B load mapping: r = tid>>4 (0..15), c4 = tid&15
    const int a_r0 = (tid) >> 2,        a_c4_0 = (tid) & 3;
    const int a_r1 = (tid + 256) >> 2,  a_c4_1 = (tid + 256) & 3;
    const int b_r  = tid >> 4,          b_c4   = tid & 15;

    auto loadG = [&](int kt) {
        // A
        {
            int gr = rowBase + a_r0, gc = kt + a_c4_0 * 4;
            float4 v = make_float4(0.f, 0.f, 0.f, 0.f);
            if (gr < M && gc < K) {
                v = *(const float4*)(A + (size_t)gr * K + gc);
                if (FUSED) {
                    float4 v2 = *(const float4*)(A2 + (size_t)gr * K + gc);
                    float s = 1.0f / (deg[gr] + 1.0f);
                    v.x = (v.x + v2.x) * s; v.y = (v.y + v2.y) * s;
                    v.z = (v.z + v2.z) * s; v.w = (v.w + v2.w) * s;
                }
            }
            ra[0] = v;
        }
        {
            int gr = rowBase + a_r1, gc = kt + a_c4_1 * 4;
            float4 v = make_float4(0.f, 0.f, 0.f, 0.f);
            if (gr < M && gc < K) {
                v = *(const float4*)(A + (size_t)gr * K + gc);
                if (FUSED) {
                    float4 v2 = *(const float4*)(A2 + (size_t)gr * K + gc);
                    float s = 1.0f / (deg[gr] + 1.0f);
                    v.x = (v.x + v2.x) * s; v.y = (v.y + v2.y) * s;
                    v.z = (v.z + v2.z) * s; v.w = (v.w + v2.w) * s;
                }
            }
            ra[1] = v;
        }
        // B
        {
            int grow = kt + b_r, gc = colBase + b_c4 * 4;
            float4 v = make_float4(0.f, 0.f, 0.f, 0.f);
            if (grow < K && gc < Ncol)
                v = *(const float4*)(B + (size_t)grow * Ncol + gc);
            rb = v;
        }
    };

    auto storeS = [&]() {
        // scatter A into fragment order
        #pragma unroll
        for (int q = 0; q < 2; q++) {
            int r  = q ? a_r1 : a_r0;
            int c4 = q ? a_c4_1 : a_c4_0;
            float vv[4] = {ra[q].x, ra[q].y, ra[q].z, ra[q].w};
            int mt = r >> 4, rl = r & 15;
            int g = rl & 7, hi = rl >> 3;
            #pragma unroll
            for (int j = 0; j < 4; j++) {
                int c = c4 * 4 + j;
                int ks = c >> 3, cl = c & 7;
                int tig = cl & 3, chi = cl >> 2;
                int slane = g * 4 + tig;
                int jj = hi + 2 * chi;
                As[(((mt * 2 + ks) * 32) + slane) * 4 + jj] = f2tf32(vv[j]);
            }
        }
        // scatter B
        {
            float vv[4] = {rb.x, rb.y, rb.z, rb.w};
            int ks = b_r >> 3, kl = b_r & 7;
            int tig = kl & 3, jj = kl >> 2;
            #pragma unroll
            for (int j = 0; j < 4; j++) {
                int c = b_c4 * 4 + j;          // 0..63
                int nt = c >> 3, nl = c & 7;
                int slane = nl * 4 + tig;
                Bs[(((nt * 2 + ks) * 32) + slane) * 2 + jj] = f2tf32(vv[j]);
            }
        }
    };

    loadG(0);
    const int KITERS = (K + GBK - 1) / GBK;
    for (int it = 0; it < KITERS; it++) {
        __syncthreads();            // previous compute done
        storeS();
        __syncthreads();
        if (it + 1 < KITERS) loadG((it + 1) * GBK);

        #pragma unroll
        for (int ks = 0; ks < 2; ks++) {
            uint4 af[2];
            #pragma unroll
            for (int i = 0; i < 2; i++) {
                int mt = wm * 2 + i;
                af[i] = *(const uint4*)&As[(((mt * 2 + ks) * 32) + lane) * 4];
            }
            uint2 bf[4];
            #pragma unroll
            for (int j = 0; j < 4; j++) {
                int nt = wn * 4 + j;
                bf[j] = *(const uint2*)&Bs[(((nt * 2 + ks) * 32) + lane) * 2];
            }
            #pragma unroll
            for (int i = 0; i < 2; i++)
                #pragma unroll
                for (int j = 0; j < 4; j++) {
                    asm volatile(
                        "mma.sync.aligned.m16n8k8.row.col.f32.tf32.tf32.f32 "
                        "{%0,%1,%2,%3}, {%4,%5,%6,%7}, {%8,%9}, {%0,%1,%2,%3};"
                        : "+f"(acc[i][j][0]), "+f"(acc[i][j][1]),
                          "+f"(acc[i][j][2]), "+f"(acc[i][j][3])
                        : "r"(af[i].x), "r"(af[i].y), "r"(af[i].z), "r"(af[i].w),
                          "r"(bf[j].x), "r"(bf[j].y));
                }
        }
    }

    // epilogue
    const int g   = lane >> 2;
    const int tig = lane & 3;
    #pragma unroll
    for (int i = 0; i < 2; i++) {
        int grow0 = rowBase + (wm * 2 + i) * 16 + g;
        #pragma unroll
        for (int j = 0; j < 4; j++) {
            int gcol = colBase + (wn * 4 + j) * 8 + tig * 2;
            if (gcol >= Ncol) continue;
            float b0 = 0.f, b1 = 0.f;
            if (bias) { b0 = bias[gcol]; b1 = bias[gcol + 1]; }
            if (grow0 < M) {
                float2 v = make_float2(acc[i][j][0] + b0, acc[i][j][1] + b1);
                *(float2*)(C + (size_t)grow0 * Ncol + gcol) = v;
            }
            if (grow0 + 8 < M) {
                float2 v = make_float2(acc[i][j][2] + b0, acc[i][j][3] + b1);
                *(float2*)(C + (size_t)(grow0 + 8) * Ncol + gcol) = v;
            }
        }
    }
}

// ---------------- el/er: per-(node,head) dot with attn_l / attn_r ----------------
__global__ void el_er_kernel(const float* __restrict__ fsrc,
                             const float* __restrict__ attn_l,
                             const float* __restrict__ attn_r,
                             float* __restrict__ el, float* __restrict__ er)
{
    int n = blockIdx.x;
    int w = threadIdx.x >> 5;      // head = warp id (4 warps)
    int lane = threadIdx.x & 31;
    const float* fr = fsrc + (size_t)n * HD + w * DD;
    const float* al = attn_l + w * DD;
    const float* ar = attn_r + w * DD;
    float sl = 0.f, sr = 0.f;
    for (int d = lane; d < DD; d += 32) {
        float f = fr[d];
        sl += f * al[d];
        sr += f * ar[d];
    }
    #pragma unroll
    for (int o = 16; o; o >>= 1) {
        sl += __shfl_down_sync(0xffffffffu, sl, o);
        sr += __shfl_down_sync(0xffffffffu, sr, o);
    }
    if (lane == 0) {
        el[n * HH + w] = sl;
        er[n * HH + w] = sr;
    }
}

// ---------------- edge scores + segment max ----------------
__global__ void edge_score_kernel(const float* __restrict__ el,
                                  const float* __restrict__ er,
                                  const int* __restrict__ src,
                                  const int* __restrict__ dst,
                                  float* __restrict__ ebuf,
                                  unsigned* __restrict__ mkey, int E)
{
    int i = blockIdx.x * blockDim.x + threadIdx.x;
    if (i >= E) return;
    int s = src[i], d = dst[i];
    float4 l = ((const float4*)el)[s];
    float4 r = ((const float4*)er)[d];
    float4 x;
    x.x = l.x + r.x; x.x = x.x > 0.f ? x.x : 0.2f * x.x;
    x.y = l.y + r.y; x.y = x.y > 0.f ? x.y : 0.2f * x.y;
    x.z = l.z + r.z; x.z = x.z > 0.f ? x.z : 0.2f * x.z;
    x.w = l.w + r.w; x.w = x.w > 0.f ? x.w : 0.2f * x.w;
    ((float4*)ebuf)[i] = x;
    atomicMax(&mkey[d * HH + 0], fkey(x.x));
    atomicMax(&mkey[d * HH + 1], fkey(x.y));
    atomicMax(&mkey[d * HH + 2], fkey(x.z));
    atomicMax(&mkey[d * HH + 3], fkey(x.w));
}

// ---------------- exp(e - m) and segment sum z ----------------
__global__ void edge_exp_kernel(float* __restrict__ ebuf,
                                const int* __restrict__ dst,
                                const unsigned* __restrict__ mkey,
                                float* __restrict__ z, int E)
{
    int i = blockIdx.x * blockDim.x + threadIdx.x;
    if (i >= E) return;
    int d = dst[i];
    float4 ev = ((const float4*)ebuf)[i];
    float4 x;
    x.x = expf(ev.x - funkey(mkey[d * HH + 0]));
    x.y = expf(ev.y - funkey(mkey[d * HH + 1]));
    x.z = expf(ev.z - funkey(mkey[d * HH + 2]));
    x.w = expf(ev.w - funkey(mkey[d * HH + 3]));
    ((float4*)ebuf)[i] = x;
    atomicAdd(&z[d * HH + 0], x.x);
    atomicAdd(&z[d * HH + 1], x.y);
    atomicAdd(&z[d * HH + 2], x.z);
    atomicAdd(&z[d * HH + 3], x.w);
}

// ---------------- GAT aggregation: warp per edge, vectorized RED ----------------
__global__ void gat_agg_kernel(const float* __restrict__ exbuf,
                               const float* __restrict__ z,
                               const float* __restrict__ fsrc,
                               const int* __restrict__ src,
                               const int* __restrict__ dst,
                               float* __restrict__ gat, int E)
{
    int e = (blockIdx.x * blockDim.x + threadIdx.x) >> 5;
    int lane = threadIdx.x & 31;
    if (e >= E) return;
    int s = src[e], d = dst[e];
    float al[4];
    #pragma unroll
    for (int h = 0; h < 4; h++)
        al[h] = exbuf[e * HH + h] / z[d * HH + h];
    const float4* fr = (const float4*)(fsrc + (size_t)s * HD);
    float* gr = gat + (size_t)d * HD;
    // 1200 floats = 300 float4; head boundaries at multiples of 75 float4s
    for (int idx = lane; idx < 300; idx += 32) {
        float a = al[idx / 75];
        float4 v = fr[idx];
        v.x *= a; v.y *= a; v.z *= a; v.w *= a;
        red_add_f32x4(gr + idx * 4, v);
    }
}

// ---------------- SAGE: warp per edge ----------------
__global__ void sage_agg_kernel(const float* __restrict__ feat,
                                const int* __restrict__ src1,
                                const int* __restrict__ dst1,
                                float* __restrict__ neigh,
                                float* __restrict__ deg, int E)
{
    int e = (blockIdx.x * blockDim.x + threadIdx.x) >> 5;
    int lane = threadIdx.x & 31;
    if (e >= E) return;
    int s = src1[e], d = dst1[e];
    const float4* fr = (const float4*)(feat + (size_t)s * DD);
    float* nr = neigh + (size_t)d * DD;
    for (int idx = lane; idx < 75; idx += 32)
        red_add_f32x4(nr + idx * 4, fr[idx]);
    if (lane == 0) atomicAdd(&deg[d], 1.0f);
}

// ---------------- gated head sum + residual ----------------
__global__ void final_kernel(const float* __restrict__ feat,
                             const float* __restrict__ gat,
                             const float* __restrict__ sage,
                             const float* __restrict__ b_gat,
                             const float* __restrict__ Whw,
                             const float* __restrict__ bhw,
                             float* __restrict__ out)
{
    int n = blockIdx.x;
    int t = threadIdx.x;            // 256 threads
    int lane = t & 31;

    __shared__ float ssum[5];
    __shared__ float sw[5];
    if (t < 5) ssum[t] = 0.f;
    __syncthreads();

    float vals[2][5];
    float p[5] = {0.f, 0.f, 0.f, 0.f, 0.f};

    #pragma unroll
    for (int it = 0; it < 2; it++) {
        int d = t + it * 256;
        if (d < DD) {
            float wv = Whw[d];
            #pragma unroll
            for (int r = 0; r < 4; r++) {
                float v = gat[(size_t)n * HD + r * DD + d] + b_gat[r * DD + d];
                vals[it][r] = v;
                p[r] += v * wv;
            }
            float v4 = sage[(size_t)n * DD + d];
            vals[it][4] = v4;
            p[4] += v4 * wv;
        }
    }
    #pragma unroll
    for (int o = 16; o; o >>= 1)
        #pragma unroll
        for (int r = 0; r < 5; r++)
            p[r] += __shfl_down_sync(0xffffffffu, p[r], o);
    if (lane == 0)
        #pragma unroll
        for (int r = 0; r < 5; r++) atomicAdd(&ssum[r], p[r]);
    __syncthreads();
    if (t < 5) sw[t] = 1.0f / (1.0f + expf(-(ssum[t] + bhw[0])));
    __syncthreads();

    float w0 = sw[0], w1 = sw[1], w2 = sw[2], w3 = sw[3], w4 = sw[4];
    #pragma unroll
    for (int it = 0; it < 2; it++) {
        int d = t + it * 256;
        if (d < DD) {
            float acc = feat[(size_t)n * DD + d];
            acc += vals[it][0] * w0 + vals[it][1] * w1 + vals[it][2] * w2
                 + vals[it][3] * w3 + vals[it][4] * w4;
            out[(size_t)n * DD + d] = acc;
        }
    }
}

// ---------------- launch ----------------
extern "C" void kernel_launch(void* const* d_in, const int* in_sizes, int n_in,
                              void* d_out, int out_size)
{
    const float* feat   = (const float*)d_in[0];
    const float* Wg     = (const float*)d_in[1];
    const float* attn_l = (const float*)d_in[2];
    const float* attn_r = (const float*)d_in[3];
    const float* b_gat  = (const float*)d_in[4];
    const float* Wsage  = (const float*)d_in[5];
    const float* b_sage = (const float*)d_in[6];
    const float* Whw    = (const float*)d_in[7];
    const float* bhw    = (const float*)d_in[8];
    const int*   src    = (const int*)d_in[9];
    const int*   dst    = (const int*)d_in[10];
    const int*   src1   = (const int*)d_in[11];
    const int*   dst1   = (const int*)d_in[12];
    float* out = (float*)d_out;

    const int N = in_sizes[0] / DD;
    const int E = in_sizes[9];

    float *fsrc, *gat, *el, *er, *ebuf, *z, *neigh, *deg, *sage;
    unsigned* mkey;
    cudaGetSymbolAddress((void**)&fsrc,  g_fsrc);
    cudaGetSymbolAddress((void**)&gat,   g_gat);
    cudaGetSymbolAddress((void**)&el,    g_el);
    cudaGetSymbolAddress((void**)&er,    g_er);
    cudaGetSymbolAddress((void**)&ebuf,  g_e);
    cudaGetSymbolAddress((void**)&mkey,  g_mkey);
    cudaGetSymbolAddress((void**)&z,     g_z);
    cudaGetSymbolAddress((void**)&neigh, g_neigh);
    cudaGetSymbolAddress((void**)&deg,   g_deg);
    cudaGetSymbolAddress((void**)&sage,  g_sage);

    // zero accumulators (graph-capturable memset nodes)
    cudaMemsetAsync(mkey,  0, (size_t)N * HH * sizeof(unsigned), 0);
    cudaMemsetAsync(z,     0, (size_t)N * HH * sizeof(float), 0);
    cudaMemsetAsync(gat,   0, (size_t)N * HD * sizeof(float), 0);
    cudaMemsetAsync(neigh, 0, (size_t)N * DD * sizeof(float), 0);
    cudaMemsetAsync(deg,   0, (size_t)N * sizeof(float), 0);

    // GEMM1: fsrc = feat @ Wg    [N,300] @ [300,1200]  (TF32 tensor cores)
    {
        dim3 grid((HD + GBN - 1) / GBN, (N + GBM - 1) / GBM);
        gemm_tf32_kernel<false><<<grid, 256>>>(feat, Wg, fsrc, N, HD, DD,
                                               nullptr, nullptr, nullptr);
    }

    // el/er
    el_er_kernel<<<N, 128>>>(fsrc, attn_l, attn_r, el, er);

    // edge softmax pipeline
    edge_score_kernel<<<(E + 255) / 256, 256>>>(el, er, src, dst, ebuf, mkey, E);
    edge_exp_kernel<<<(E + 255) / 256, 256>>>(ebuf, dst, mkey, z, E);
    gat_agg_kernel<<<(E + 7) / 8, 256>>>(ebuf, z, fsrc, src, dst, gat, E);

    // SAGE aggregation (independent graph g1)
    sage_agg_kernel<<<(E + 7) / 8, 256>>>(feat, src1, dst1, neigh, deg, E);

    // GEMM2: sage = ((neigh + feat)/(deg+1)) @ Wsage + b_sage   [N,300]@[300,300]
    {
        dim3 grid((DD + GBN - 1) / GBN, (N + GBM - 1) / GBM);
        gemm_tf32_kernel<true><<<grid, 256>>>(neigh, Wsage, sage, N, DD, DD,
                                              feat, deg, b_sage);
    }

    // gated multi-head sum + residual
    final_kernel<<<N, 256>>>(feat, gat, sage, b_gat, Whw, bhw, out);
}